// round 1
// baseline (speedup 1.0000x reference)
#include <cuda_runtime.h>

// ---------------- problem constants ----------------
#define B_   2
#define N_   2048
#define E_   1024
#define H_   16
#define D_   64
#define SCALE_ 0.125f   // 64^-0.5

// ---------------- device scratch (no allocs allowed) ----------------
__device__ float g_q[(size_t)B_*H_*N_*D_];
__device__ float g_k[(size_t)B_*H_*N_*D_];
__device__ float g_v[(size_t)B_*H_*N_*D_];
__device__ float g_attn[(size_t)B_*N_*E_];

// =====================================================================
// SGEMM (NT):  C[m,n] = sum_k A[m,k] * Bw[n,k] + bias[n]
// 128x128 block tile, BK=16, 256 threads, 8x8 per thread (split 4+4).
// MODE 0: A = x, epilogue scatters into g_q/g_k/g_v ([B,H,N,D])
// MODE 1: A = g_attn, epilogue writes C row-major [M,N]
// =====================================================================
#define GBM 128
#define GBN 128
#define GBK 16
#define GLDS 132   // 128 + 4 pad, multiple of 4 for float4

template<int MODE>
__global__ __launch_bounds__(256, 2)
void sgemm_nt(const float* __restrict__ A_in, const float* __restrict__ Bw,
              const float* __restrict__ bias, float* __restrict__ C,
              int M, int N, int K)
{
    __shared__ float As[GBK][GLDS];
    __shared__ float Bs[GBK][GLDS];

    const float* A = (MODE == 0) ? A_in : g_attn;

    int tid = threadIdx.x;
    int m0 = blockIdx.y * GBM;
    int n0 = blockIdx.x * GBN;
    int ty = tid >> 4;        // 0..15
    int tx = tid & 15;        // 0..15

    float acc[8][8];
#pragma unroll
    for (int i = 0; i < 8; i++)
#pragma unroll
        for (int j = 0; j < 8; j++) acc[i][j] = 0.f;

    for (int k0 = 0; k0 < K; k0 += GBK) {
        // load A tile (128 rows x 16 k) transposed into As[k][m]
#pragma unroll
        for (int l = 0; l < 2; l++) {
            int idx = tid + l * 256;         // 0..511
            int row = idx >> 2;              // 0..127
            int kc  = (idx & 3) << 2;        // 0,4,8,12
            float4 v = *(const float4*)&A[(size_t)(m0 + row) * K + k0 + kc];
            As[kc + 0][row] = v.x; As[kc + 1][row] = v.y;
            As[kc + 2][row] = v.z; As[kc + 3][row] = v.w;
        }
#pragma unroll
        for (int l = 0; l < 2; l++) {
            int idx = tid + l * 256;
            int row = idx >> 2;
            int kc  = (idx & 3) << 2;
            float4 v = *(const float4*)&Bw[(size_t)(n0 + row) * K + k0 + kc];
            Bs[kc + 0][row] = v.x; Bs[kc + 1][row] = v.y;
            Bs[kc + 2][row] = v.z; Bs[kc + 3][row] = v.w;
        }
        __syncthreads();

#pragma unroll
        for (int k = 0; k < GBK; k++) {
            float a[8], b[8];
            *(float4*)&a[0] = *(const float4*)&As[k][ty * 4];
            *(float4*)&a[4] = *(const float4*)&As[k][64 + ty * 4];
            *(float4*)&b[0] = *(const float4*)&Bs[k][tx * 4];
            *(float4*)&b[4] = *(const float4*)&Bs[k][64 + tx * 4];
#pragma unroll
            for (int i = 0; i < 8; i++)
#pragma unroll
                for (int j = 0; j < 8; j++)
                    acc[i][j] += a[i] * b[j];
        }
        __syncthreads();
    }

    // epilogue
#pragma unroll
    for (int ih = 0; ih < 2; ih++) {
#pragma unroll
        for (int ii = 0; ii < 4; ii++) {
            int i = ih * 4 + ii;
            int m = m0 + ih * 64 + ty * 4 + ii;
#pragma unroll
            for (int jh = 0; jh < 2; jh++) {
                int nb = n0 + jh * 64 + tx * 4;   // 4 consecutive cols
                float4 bv = *(const float4*)&bias[nb];
                float4 v;
                v.x = acc[i][jh * 4 + 0] + bv.x;
                v.y = acc[i][jh * 4 + 1] + bv.y;
                v.z = acc[i][jh * 4 + 2] + bv.z;
                v.w = acc[i][jh * 4 + 3] + bv.w;
                if (MODE == 0) {
                    // scatter into q/k/v:  [b][h][nn][d]
                    int bb = m >> 11, nn = m & (N_ - 1);
                    int which = nb >> 10, e = nb & 1023;
                    int h = e >> 6, d = e & 63;   // d..d+3 stays in one head
                    float* dst = (which == 0) ? g_q : ((which == 1) ? g_k : g_v);
                    *(float4*)&dst[(((size_t)bb * H_ + h) * N_ + nn) * D_ + d] = v;
                } else {
                    *(float4*)&C[(size_t)m * N + nb] = v;
                }
            }
        }
    }
}

// =====================================================================
// Flash attention (fp32 SIMT, causal).
// One block per (q-tile of 64, b*h). 256 threads, 4x4 per thread.
// smem: Qt[d][r] (Q^T, pre-scaled), KV (K^T then V row-major), Pt[k][r],
//       red[64][16] reductions, m/fac/l stats.
// =====================================================================
#define ALD 68   // 64 + 4 pad (multiple of 4)

__global__ __launch_bounds__(256)
void attention_kernel()
{
    extern __shared__ float smem[];
    float* Qt  = smem;                     // 64 * ALD
    float* KV  = smem + 64 * ALD;          // 64 * ALD  (K^T, then V)
    float* Pt  = smem + 2 * 64 * ALD;      // 64 * ALD  (P transposed [key][row])
    float* red = smem + 3 * 64 * ALD;      // 64 * 16
    float* mst = red + 64 * 16;            // 64
    float* fac = mst + 64;                 // 64
    float* lst = fac + 64;                 // 64

    int tid = threadIdx.x;
    int ty = tid >> 4;     // 0..15 -> rows ty*4..ty*4+3
    int tx = tid & 15;     // 0..15 -> cols tx*4..tx*4+3
    int qt = blockIdx.x;   // q tile 0..31
    int bh = blockIdx.y;   // 0..31 = b*16 + h

    const float* Qg = g_q + (size_t)bh * N_ * D_;
    const float* Kg = g_k + (size_t)bh * N_ * D_;
    const float* Vg = g_v + (size_t)bh * N_ * D_;

    // load Q tile transposed + pre-scaled
#pragma unroll
    for (int l = 0; l < 4; l++) {
        int idx = tid + l * 256;        // 0..1023
        int r  = idx >> 4;              // 0..63
        int d0 = (idx & 15) << 2;       // 0..60
        float4 v = *(const float4*)&Qg[(size_t)(qt * 64 + r) * D_ + d0];
        Qt[(d0 + 0) * ALD + r] = v.x * SCALE_;
        Qt[(d0 + 1) * ALD + r] = v.y * SCALE_;
        Qt[(d0 + 2) * ALD + r] = v.z * SCALE_;
        Qt[(d0 + 3) * ALD + r] = v.w * SCALE_;
    }
    if (tid < 64) { mst[tid] = -3.0e38f; lst[tid] = 0.f; }

    float o[4][4];
#pragma unroll
    for (int i = 0; i < 4; i++)
#pragma unroll
        for (int j = 0; j < 4; j++) o[i][j] = 0.f;

    for (int kt = 0; kt <= qt; kt++) {
        __syncthreads();   // S1: previous PV reads (and Q load) complete

        // load K tile transposed: KV[d][key]
#pragma unroll
        for (int l = 0; l < 4; l++) {
            int idx = tid + l * 256;
            int c  = idx >> 4;
            int d0 = (idx & 15) << 2;
            float4 v = *(const float4*)&Kg[(size_t)(kt * 64 + c) * D_ + d0];
            KV[(d0 + 0) * ALD + c] = v.x;
            KV[(d0 + 1) * ALD + c] = v.y;
            KV[(d0 + 2) * ALD + c] = v.z;
            KV[(d0 + 3) * ALD + c] = v.w;
        }
        __syncthreads();   // S2: K ready

        // S = Q K^T
        float s[4][4];
#pragma unroll
        for (int i = 0; i < 4; i++)
#pragma unroll
            for (int j = 0; j < 4; j++) s[i][j] = 0.f;
#pragma unroll 8
        for (int d = 0; d < 64; d++) {
            float4 a = *(const float4*)&Qt[d * ALD + ty * 4];
            float4 b = *(const float4*)&KV[d * ALD + tx * 4];
            float av[4] = {a.x, a.y, a.z, a.w};
            float bv[4] = {b.x, b.y, b.z, b.w};
#pragma unroll
            for (int i = 0; i < 4; i++)
#pragma unroll
                for (int j = 0; j < 4; j++)
                    s[i][j] += av[i] * bv[j];
        }
        if (kt == qt) {
#pragma unroll
            for (int i = 0; i < 4; i++)
#pragma unroll
                for (int j = 0; j < 4; j++)
                    if (tx * 4 + j > ty * 4 + i) s[i][j] = -3.0e38f;
        }
        __syncthreads();   // S3: K reads done -> KV reusable for V

        // local row max
#pragma unroll
        for (int i = 0; i < 4; i++) {
            float lm = s[i][0];
            lm = fmaxf(lm, s[i][1]); lm = fmaxf(lm, s[i][2]); lm = fmaxf(lm, s[i][3]);
            red[(ty * 4 + i) * 16 + tx] = lm;
        }
        // load V tile row-major: KV[key][d]
#pragma unroll
        for (int l = 0; l < 4; l++) {
            int idx = tid + l * 256;
            int c  = idx >> 4;
            int d0 = (idx & 15) << 2;
            float4 v = *(const float4*)&Vg[(size_t)(kt * 64 + c) * D_ + d0];
            *(float4*)&KV[c * ALD + d0] = v;
        }
        __syncthreads();   // S4: red + V ready

        if (tid < 64) {
            float rm = red[tid * 16];
#pragma unroll
            for (int t = 1; t < 16; t++) rm = fmaxf(rm, red[tid * 16 + t]);
            float mo = mst[tid];
            float mn = fmaxf(mo, rm);
            mst[tid] = mn;
            fac[tid] = __expf(mo - mn);
        }
        __syncthreads();   // S5: stats ready

#pragma unroll
        for (int i = 0; i < 4; i++) {
            int r = ty * 4 + i;
            float mn = mst[r];
            float f  = fac[r];
            float sum = 0.f;
#pragma unroll
            for (int j = 0; j < 4; j++) {
                float p = __expf(s[i][j] - mn);
                Pt[(tx * 4 + j) * ALD + r] = p;
                sum += p;
            }
            red[r * 16 + tx] = sum;
#pragma unroll
            for (int j = 0; j < 4; j++) o[i][j] *= f;
        }
        __syncthreads();   // S6: Pt + row sums ready

        if (tid < 64) {
            float ssum = 0.f;
#pragma unroll
            for (int t = 0; t < 16; t++) ssum += red[tid * 16 + t];
            lst[tid] = lst[tid] * fac[tid] + ssum;
        }

        // O += P V   (Pt[key][row], KV[key][d])
#pragma unroll 8
        for (int c = 0; c < 64; c++) {
            float4 a = *(const float4*)&Pt[c * ALD + ty * 4];
            float4 b = *(const float4*)&KV[c * ALD + tx * 4];
            float av[4] = {a.x, a.y, a.z, a.w};
            float bv[4] = {b.x, b.y, b.z, b.w};
#pragma unroll
            for (int i = 0; i < 4; i++)
#pragma unroll
                for (int j = 0; j < 4; j++)
                    o[i][j] += av[i] * bv[j];
        }
    }
    __syncthreads();   // lst final

    // normalize + store to g_attn [B, N, E] with head-interleave
    int b = bh >> 4, h = bh & 15;
#pragma unroll
    for (int i = 0; i < 4; i++) {
        int r = ty * 4 + i;
        float inv = 1.f / lst[r];
        int n = qt * 64 + r;
        float4 v;
        v.x = o[i][0] * inv; v.y = o[i][1] * inv;
        v.z = o[i][2] * inv; v.w = o[i][3] * inv;
        *(float4*)&g_attn[((size_t)b * N_ + n) * E_ + h * D_ + tx * 4] = v;
    }
}

// =====================================================================
// launch
// =====================================================================
extern "C" void kernel_launch(void* const* d_in, const int* in_sizes, int n_in,
                              void* d_out, int out_size)
{
    const float* x     = (const float*)d_in[0];
    const float* qkv_w = (const float*)d_in[1];
    const float* qkv_b = (const float*)d_in[2];
    const float* out_w = (const float*)d_in[3];
    const float* out_b = (const float*)d_in[4];
    float* out = (float*)d_out;

    const int M = B_ * N_;     // 4096

    // 1) QKV projection + scatter to [B,H,N,D]
    {
        dim3 grid(3 * E_ / GBN, M / GBM);   // 24 x 32
        sgemm_nt<0><<<grid, 256>>>(x, qkv_w, qkv_b, nullptr, M, 3 * E_, E_);
    }

    // 2) causal flash attention
    {
        size_t shmem = (3 * 64 * ALD + 64 * 16 + 3 * 64) * sizeof(float);
        cudaFuncSetAttribute(attention_kernel,
                             cudaFuncAttributeMaxDynamicSharedMemorySize,
                             (int)shmem);
        attention_kernel<<<dim3(N_ / 64, B_ * H_), 256, shmem>>>();
    }

    // 3) output projection
    {
        dim3 grid(E_ / GBN, M / GBM);       // 8 x 32
        sgemm_nt<1><<<grid, 256>>>(nullptr, out_w, out_b, out, M, E_, E_);
    }
}

// round 3
// speedup vs baseline: 2.8063x; 2.8063x over previous
#include <cuda_runtime.h>
#include <cuda_bf16.h>
#include <cstdint>

// ---------------- problem constants ----------------
#define B_   2
#define N_   2048
#define E_   1024
#define H_   16
#define D_   64
#define SCALE_ 0.125f   // 64^-0.5

// ---------------- device scratch (no allocs allowed) ----------------
// bf16 hi/lo split buffers
__device__ __nv_bfloat16 g_x_hi[(size_t)B_*N_*E_];
__device__ __nv_bfloat16 g_x_lo[(size_t)B_*N_*E_];
__device__ __nv_bfloat16 g_w_hi[(size_t)3*E_*E_];
__device__ __nv_bfloat16 g_w_lo[(size_t)3*E_*E_];
__device__ __nv_bfloat16 g_ow_hi[(size_t)E_*E_];
__device__ __nv_bfloat16 g_ow_lo[(size_t)E_*E_];
// q/k/v in [B,H,N,D], bf16 hi/lo (written by QKV GEMM epilogue)
__device__ __nv_bfloat16 g_qh[(size_t)B_*H_*N_*D_];
__device__ __nv_bfloat16 g_ql[(size_t)B_*H_*N_*D_];
__device__ __nv_bfloat16 g_kh[(size_t)B_*H_*N_*D_];
__device__ __nv_bfloat16 g_kl[(size_t)B_*H_*N_*D_];
__device__ __nv_bfloat16 g_vh[(size_t)B_*H_*N_*D_];
__device__ __nv_bfloat16 g_vl[(size_t)B_*H_*N_*D_];
// attention output, bf16 hi/lo [B,N,E]
__device__ __nv_bfloat16 g_at_hi[(size_t)B_*N_*E_];
__device__ __nv_bfloat16 g_at_lo[(size_t)B_*N_*E_];

// =====================================================================
// helpers
// =====================================================================
__device__ __forceinline__ uint32_t smem_u32(const void* p) {
    uint32_t a;
    asm("{ .reg .u64 t; cvta.to.shared.u64 t, %1; cvt.u32.u64 %0, t; }" : "=r"(a) : "l"(p));
    return a;
}
__device__ __forceinline__ uint32_t sw128(uint32_t off) { return off ^ ((off >> 3) & 0x70); }

__device__ __forceinline__ void cpa16(uint32_t dst, const void* src) {
    asm volatile("cp.async.cg.shared.global [%0], [%1], 16;" :: "r"(dst), "l"(src));
}
#define CPC() asm volatile("cp.async.commit_group;" ::: "memory")
#define CPW(n) asm volatile("cp.async.wait_group %0;" :: "n"(n) : "memory")

__device__ __forceinline__ void ldsm4(uint32_t addr, uint32_t* r) {
    asm volatile("ldmatrix.sync.aligned.m8n8.x4.shared.b16 {%0,%1,%2,%3}, [%4];"
        : "=r"(r[0]), "=r"(r[1]), "=r"(r[2]), "=r"(r[3]) : "r"(addr));
}
__device__ __forceinline__ void ldsm4t(uint32_t addr, uint32_t* r) {
    asm volatile("ldmatrix.sync.aligned.m8n8.x4.trans.shared.b16 {%0,%1,%2,%3}, [%4];"
        : "=r"(r[0]), "=r"(r[1]), "=r"(r[2]), "=r"(r[3]) : "r"(addr));
}
__device__ __forceinline__ void mma16816(float* c, const uint32_t* a, uint32_t b0, uint32_t b1) {
    asm volatile(
        "mma.sync.aligned.m16n8k16.row.col.f32.bf16.bf16.f32 "
        "{%0,%1,%2,%3},{%4,%5,%6,%7},{%8,%9},{%0,%1,%2,%3};"
        : "+f"(c[0]), "+f"(c[1]), "+f"(c[2]), "+f"(c[3])
        : "r"(a[0]), "r"(a[1]), "r"(a[2]), "r"(a[3]), "r"(b0), "r"(b1));
}

__device__ __forceinline__ uint32_t pack_hi2(float v0, float v1) {
    __nv_bfloat162 h;
    h.x = __float2bfloat16(v0);
    h.y = __float2bfloat16(v1);
    return *(uint32_t*)&h;
}
__device__ __forceinline__ uint32_t pack_lo2(float v0, float v1) {
    __nv_bfloat16 h0 = __float2bfloat16(v0);
    __nv_bfloat16 h1 = __float2bfloat16(v1);
    __nv_bfloat162 l;
    l.x = __float2bfloat16(v0 - __bfloat162float(h0));
    l.y = __float2bfloat16(v1 - __bfloat162float(h1));
    return *(uint32_t*)&l;
}

// =====================================================================
// split kernel: fp32 -> bf16 hi + bf16 lo   (W selects dest globals)
// =====================================================================
template<int W>
__global__ void split_kernel(const float* __restrict__ src, int n4)
{
    __nv_bfloat16* hi = (W == 0) ? g_x_hi : (W == 1) ? g_w_hi : g_ow_hi;
    __nv_bfloat16* lo = (W == 0) ? g_x_lo : (W == 1) ? g_w_lo : g_ow_lo;
    int i = blockIdx.x * blockDim.x + threadIdx.x;
    if (i >= n4) return;
    float4 a = *(const float4*)&src[(size_t)i * 4];
    uint32_t h01 = pack_hi2(a.x, a.y), h23 = pack_hi2(a.z, a.w);
    uint32_t l01 = pack_lo2(a.x, a.y), l23 = pack_lo2(a.z, a.w);
    uint2 hv = {h01, h23}, lv = {l01, l23};
    *(uint2*)&hi[(size_t)i * 4] = hv;
    *(uint2*)&lo[(size_t)i * 4] = lv;
}

// =====================================================================
// mma.sync GEMM (NT), bf16x3 split:
// C[m,n] = sum_k A[m,k]*Bw[n,k] + bias[n]
// BM=128, BN=128, BK=64. 256 threads (8 warps, warp tile 32x64).
// Double-buffered cp.async. SW128 swizzled smem (128B rows).
// MODE 0: A=g_x, B=g_w,  epilogue -> g_q/k/v hi/lo (scatter [B,H,N,D])
// MODE 1: A=g_at, B=g_ow, epilogue -> fp32 C row-major
// =====================================================================
#define GT_TILE 16384                // 128 rows * 128B
#define GT_STAGE (4 * GT_TILE)       // Ah, Al, Bh, Bl

extern __shared__ __align__(16) char dyn_smem[];

template<int MODE>
__global__ __launch_bounds__(256, 1)
void gemm_mma(const float* __restrict__ bias, float* __restrict__ C, int K, int Nout)
{
    const __nv_bfloat16* Ah = (MODE == 0) ? g_x_hi : g_at_hi;
    const __nv_bfloat16* Al = (MODE == 0) ? g_x_lo : g_at_lo;
    const __nv_bfloat16* Bh = (MODE == 0) ? g_w_hi : g_ow_hi;
    const __nv_bfloat16* Bl = (MODE == 0) ? g_w_lo : g_ow_lo;

    char* sm = (char*)(((uintptr_t)dyn_smem + 1023) & ~(uintptr_t)1023);
    uint32_t sb = smem_u32(sm);

    int tid = threadIdx.x;
    int lane = tid & 31;
    int wid = tid >> 5;
    int wm = wid >> 1;               // 0..3 -> rows wm*32
    int wn = wid & 1;                // 0..1 -> cols wn*64
    int m0 = blockIdx.y * 128;
    int n0 = blockIdx.x * 128;

    float acc[2][8][4];
#pragma unroll
    for (int a = 0; a < 2; a++)
#pragma unroll
        for (int b = 0; b < 8; b++)
#pragma unroll
            for (int c = 0; c < 4; c++) acc[a][b][c] = 0.f;

    const __nv_bfloat16* gsrc[4] = {Ah, Al, Bh, Bl};
    const int rb[4] = {m0, m0, n0, n0};

    auto load_stage = [&](int s, int k0) {
#pragma unroll
        for (int t = 0; t < 4; t++) {
#pragma unroll
            for (int l = 0; l < 4; l++) {
                int idx = tid + l * 256;        // 0..1023
                int row = idx >> 3;             // 0..127
                int seg = idx & 7;              // 0..7
                const void* src = gsrc[t] + (size_t)(rb[t] + row) * K + k0 + seg * 8;
                uint32_t off = sw128((uint32_t)(row * 128 + seg * 16));
                cpa16(sb + s * GT_STAGE + t * GT_TILE + off, src);
            }
        }
        CPC();
    };

    const int NIT = K / 64;
    load_stage(0, 0);

    for (int it = 0; it < NIT; it++) {
        int s = it & 1;
        if (it + 1 < NIT) { load_stage(s ^ 1, (it + 1) * 64); CPW(1); }
        else              { CPW(0); }
        __syncthreads();

        uint32_t aH = sb + s * GT_STAGE;
        uint32_t aL = aH + GT_TILE;
        uint32_t bH = aH + 2 * GT_TILE;
        uint32_t bL = aH + 3 * GT_TILE;

#pragma unroll
        for (int ks = 0; ks < 4; ks++) {
            int koff = (ks * 16 + (lane >> 4) * 8) * 2;
            uint32_t ah[2][4], al[2][4];
#pragma unroll
            for (int tm = 0; tm < 2; tm++) {
                int ar = wm * 32 + tm * 16 + (lane & 15);
                uint32_t off = sw128((uint32_t)(ar * 128 + koff));
                ldsm4(aH + off, ah[tm]);
                ldsm4(aL + off, al[tm]);
            }
#pragma unroll
            for (int u = 0; u < 4; u++) {
                int br = wn * 64 + u * 16 + (lane & 15);
                uint32_t off = sw128((uint32_t)(br * 128 + koff));
                uint32_t bh4[4], bl4[4];
                ldsm4(bH + off, bh4);
                ldsm4(bL + off, bl4);
#pragma unroll
                for (int tm = 0; tm < 2; tm++) {
                    mma16816(acc[tm][2*u],   ah[tm], bh4[0], bh4[2]);
                    mma16816(acc[tm][2*u],   ah[tm], bl4[0], bl4[2]);
                    mma16816(acc[tm][2*u],   al[tm], bh4[0], bh4[2]);
                    mma16816(acc[tm][2*u+1], ah[tm], bh4[1], bh4[3]);
                    mma16816(acc[tm][2*u+1], ah[tm], bl4[1], bl4[3]);
                    mma16816(acc[tm][2*u+1], al[tm], bh4[1], bh4[3]);
                }
            }
        }
        __syncthreads();
    }

    // ---- epilogue ----
#pragma unroll
    for (int tm = 0; tm < 2; tm++) {
#pragma unroll
        for (int j = 0; j < 8; j++) {
            int nb = n0 + wn * 64 + j * 8 + (lane & 3) * 2;
            float2 bv = *(const float2*)&bias[nb];
#pragma unroll
            for (int half = 0; half < 2; half++) {
                int m = m0 + wm * 32 + tm * 16 + (lane >> 2) + half * 8;
                float v0 = acc[tm][j][half * 2 + 0] + bv.x;
                float v1 = acc[tm][j][half * 2 + 1] + bv.y;
                if (MODE == 0) {
                    int bb = m >> 11, nn = m & (N_ - 1);
                    int which = nb >> 10, e = nb & 1023;
                    int h = e >> 6, d = e & 63;
                    __nv_bfloat16* dh = (which == 0) ? g_qh : (which == 1) ? g_kh : g_vh;
                    __nv_bfloat16* dl = (which == 0) ? g_ql : (which == 1) ? g_kl : g_vl;
                    size_t idx = (((size_t)bb * H_ + h) * N_ + nn) * D_ + d;
                    *(uint32_t*)&dh[idx] = pack_hi2(v0, v1);
                    *(uint32_t*)&dl[idx] = pack_lo2(v0, v1);
                } else {
                    float2 v = {v0, v1};
                    *(float2*)&C[(size_t)m * Nout + nb] = v;
                }
            }
        }
    }
}

// =====================================================================
// Flash attention, mma.sync bf16x3.
// Block = 128 threads (4 warps), q-tile 64 rows (16 per warp), D=64.
// smem tiles (8KB each, SW128): [P(h), P(l) (reused Q), Kh, Kl, Vh, Vl]
// =====================================================================
__global__ __launch_bounds__(128, 2)
void attention_kernel()
{
    char* sm = (char*)(((uintptr_t)dyn_smem + 1023) & ~(uintptr_t)1023);
    uint32_t sb = smem_u32(sm);
    const uint32_t Pha = sb;
    const uint32_t Pla = sb + 8192;
    const uint32_t Kha = sb + 16384;
    const uint32_t Kla = sb + 24576;
    const uint32_t Vha = sb + 32768;
    const uint32_t Vla = sb + 40960;

    int tid = threadIdx.x;
    int lane = tid & 31;
    int wid = tid >> 5;
    int qt = blockIdx.x;
    int bh = blockIdx.y;
    size_t base = (size_t)bh * N_ * D_;

    // ---- load Q tile (hi/lo) into P region ----
#pragma unroll
    for (int l = 0; l < 4; l++) {
        int idx = tid + l * 128;        // 0..511
        int row = idx >> 3;             // 0..63
        int seg = idx & 7;
        size_t go = base + (size_t)(qt * 64 + row) * D_ + seg * 8;
        uint32_t off = sw128((uint32_t)(row * 128 + seg * 16));
        cpa16(Pha + off, g_qh + go);
        cpa16(Pla + off, g_ql + go);
    }
    CPC(); CPW(0);
    __syncthreads();

    // ---- Q fragments into registers (per-warp 16 rows) ----
    uint32_t qh[4][4], qlr[4][4];
    int ar = wid * 16 + (lane & 15);
#pragma unroll
    for (int ks = 0; ks < 4; ks++) {
        uint32_t off = sw128((uint32_t)(ar * 128 + (ks * 16 + (lane >> 4) * 8) * 2));
        ldsm4(Pha + off, qh[ks]);
        ldsm4(Pla + off, qlr[ks]);
    }

    float o[8][4];
#pragma unroll
    for (int j = 0; j < 8; j++)
#pragma unroll
        for (int e = 0; e < 4; e++) o[j][e] = 0.f;
    float m0r = -1e30f, m1r = -1e30f, l0 = 0.f, l1 = 0.f;

    int r0 = lane >> 2;
    int rowl0 = wid * 16 + r0;
    int rowl1 = rowl0 + 8;

    for (int kt = 0; kt <= qt; kt++) {
        __syncthreads();   // previous iter's K/V & P reads done

        // ---- K tiles (group A), V tiles (group B) ----
#pragma unroll
        for (int l = 0; l < 4; l++) {
            int idx = tid + l * 128;
            int row = idx >> 3, seg = idx & 7;
            size_t go = base + (size_t)(kt * 64 + row) * D_ + seg * 8;
            uint32_t off = sw128((uint32_t)(row * 128 + seg * 16));
            cpa16(Kha + off, g_kh + go);
            cpa16(Kla + off, g_kl + go);
        }
        CPC();
#pragma unroll
        for (int l = 0; l < 4; l++) {
            int idx = tid + l * 128;
            int row = idx >> 3, seg = idx & 7;
            size_t go = base + (size_t)(kt * 64 + row) * D_ + seg * 8;
            uint32_t off = sw128((uint32_t)(row * 128 + seg * 16));
            cpa16(Vha + off, g_vh + go);
            cpa16(Vla + off, g_vl + go);
        }
        CPC();
        CPW(1);            // K ready (V may still be in flight)
        __syncthreads();

        // ---- S = Q K^T (3-term) ----
        float sc[8][4];
#pragma unroll
        for (int j = 0; j < 8; j++)
#pragma unroll
            for (int e = 0; e < 4; e++) sc[j][e] = 0.f;

#pragma unroll
        for (int ks = 0; ks < 4; ks++) {
            int koff = (ks * 16 + (lane >> 4) * 8) * 2;
#pragma unroll
            for (int u = 0; u < 4; u++) {
                int br = u * 16 + (lane & 15);
                uint32_t off = sw128((uint32_t)(br * 128 + koff));
                uint32_t kh4[4], kl4[4];
                ldsm4(Kha + off, kh4);
                ldsm4(Kla + off, kl4);
                mma16816(sc[2*u],   qh[ks],  kh4[0], kh4[2]);
                mma16816(sc[2*u],   qh[ks],  kl4[0], kl4[2]);
                mma16816(sc[2*u],   qlr[ks], kh4[0], kh4[2]);
                mma16816(sc[2*u+1], qh[ks],  kh4[1], kh4[3]);
                mma16816(sc[2*u+1], qh[ks],  kl4[1], kl4[3]);
                mma16816(sc[2*u+1], qlr[ks], kh4[1], kh4[3]);
            }
        }

        // scale + causal mask
#pragma unroll
        for (int j = 0; j < 8; j++) {
#pragma unroll
            for (int e = 0; e < 4; e++) sc[j][e] *= SCALE_;
        }
        if (kt == qt) {
#pragma unroll
            for (int j = 0; j < 8; j++) {
                int c = j * 8 + (lane & 3) * 2;
                if (c     > rowl0) sc[j][0] = -1e30f;
                if (c + 1 > rowl0) sc[j][1] = -1e30f;
                if (c     > rowl1) sc[j][2] = -1e30f;
                if (c + 1 > rowl1) sc[j][3] = -1e30f;
            }
        }

        // ---- online softmax ----
        float t0 = -1e30f, t1 = -1e30f;
#pragma unroll
        for (int j = 0; j < 8; j++) {
            t0 = fmaxf(t0, fmaxf(sc[j][0], sc[j][1]));
            t1 = fmaxf(t1, fmaxf(sc[j][2], sc[j][3]));
        }
        t0 = fmaxf(t0, __shfl_xor_sync(0xffffffff, t0, 1));
        t0 = fmaxf(t0, __shfl_xor_sync(0xffffffff, t0, 2));
        t1 = fmaxf(t1, __shfl_xor_sync(0xffffffff, t1, 1));
        t1 = fmaxf(t1, __shfl_xor_sync(0xffffffff, t1, 2));
        float nm0 = fmaxf(m0r, t0), nm1 = fmaxf(m1r, t1);
        float f0 = __expf(m0r - nm0), f1 = __expf(m1r - nm1);
        m0r = nm0; m1r = nm1;

        float s0 = 0.f, s1 = 0.f;
#pragma unroll
        for (int j = 0; j < 8; j++) {
            float p0 = __expf(sc[j][0] - nm0);
            float p1 = __expf(sc[j][1] - nm0);
            float p2 = __expf(sc[j][2] - nm1);
            float p3 = __expf(sc[j][3] - nm1);
            s0 += p0 + p1; s1 += p2 + p3;
            uint32_t coff = (uint32_t)(j * 16 + (lane & 3) * 4);
            uint32_t off0 = sw128((uint32_t)(rowl0 * 128) + coff);
            uint32_t off1 = sw128((uint32_t)(rowl1 * 128) + coff);
            *(uint32_t*)(sm + (Pha - sb) + off0) = pack_hi2(p0, p1);
            *(uint32_t*)(sm + (Pla - sb) + off0) = pack_lo2(p0, p1);
            *(uint32_t*)(sm + (Pha - sb) + off1) = pack_hi2(p2, p3);
            *(uint32_t*)(sm + (Pla - sb) + off1) = pack_lo2(p2, p3);
            o[j][0] *= f0; o[j][1] *= f0; o[j][2] *= f1; o[j][3] *= f1;
        }
        s0 += __shfl_xor_sync(0xffffffff, s0, 1);
        s0 += __shfl_xor_sync(0xffffffff, s0, 2);
        s1 += __shfl_xor_sync(0xffffffff, s1, 1);
        s1 += __shfl_xor_sync(0xffffffff, s1, 2);
        l0 = l0 * f0 + s0;
        l1 = l1 * f1 + s1;
        __syncwarp();

        CPW(0);            // V ready
        __syncthreads();

        // ---- O += P V (3-term) ----
#pragma unroll
        for (int ks = 0; ks < 4; ks++) {
            uint32_t offp = sw128((uint32_t)(ar * 128 + (ks * 16 + (lane >> 4) * 8) * 2));
            uint32_t ph4[4], pl4[4];
            ldsm4(Pha + offp, ph4);
            ldsm4(Pla + offp, pl4);
#pragma unroll
            for (int u = 0; u < 4; u++) {
                int vr = ks * 16 + ((lane >> 4) << 3) + (lane & 7);
                int vc = u * 16 + ((lane >> 3) & 1) * 8;
                uint32_t offv = sw128((uint32_t)(vr * 128 + vc * 2));
                uint32_t vh4[4], vl4[4];
                ldsm4t(Vha + offv, vh4);
                ldsm4t(Vla + offv, vl4);
                mma16816(o[2*u],   ph4, vh4[0], vh4[2]);
                mma16816(o[2*u],   ph4, vl4[0], vl4[2]);
                mma16816(o[2*u],   pl4, vh4[0], vh4[2]);
                mma16816(o[2*u+1], ph4, vh4[1], vh4[3]);
                mma16816(o[2*u+1], ph4, vl4[1], vl4[3]);
                mma16816(o[2*u+1], pl4, vh4[1], vh4[3]);
            }
        }
    }

    // ---- epilogue: normalize + write bf16 hi/lo [B,N,E] ----
    float inv0 = 1.f / l0, inv1 = 1.f / l1;
    int b = bh >> 4, h = bh & 15;
    int n0g = qt * 64 + rowl0;
#pragma unroll
    for (int j = 0; j < 8; j++) {
        int d = h * 64 + j * 8 + (lane & 3) * 2;
        size_t i0 = ((size_t)b * N_ + n0g) * E_ + d;
        size_t i1 = ((size_t)b * N_ + n0g + 8) * E_ + d;
        *(uint32_t*)&g_at_hi[i0] = pack_hi2(o[j][0] * inv0, o[j][1] * inv0);
        *(uint32_t*)&g_at_lo[i0] = pack_lo2(o[j][0] * inv0, o[j][1] * inv0);
        *(uint32_t*)&g_at_hi[i1] = pack_hi2(o[j][2] * inv1, o[j][3] * inv1);
        *(uint32_t*)&g_at_lo[i1] = pack_lo2(o[j][2] * inv1, o[j][3] * inv1);
    }
}

// =====================================================================
// launch
// =====================================================================
extern "C" void kernel_launch(void* const* d_in, const int* in_sizes, int n_in,
                              void* d_out, int out_size)
{
    const float* x     = (const float*)d_in[0];
    const float* qkv_w = (const float*)d_in[1];
    const float* qkv_b = (const float*)d_in[2];
    const float* out_w = (const float*)d_in[3];
    const float* out_b = (const float*)d_in[4];
    float* out = (float*)d_out;

    const int M = B_ * N_;                       // 4096
    const int gemm_smem = 2 * GT_STAGE + 1024;   // 129 KB
    const int attn_smem = 6 * 8192 + 1024;       // 49 KB

    cudaFuncSetAttribute(gemm_mma<0>, cudaFuncAttributeMaxDynamicSharedMemorySize, gemm_smem);
    cudaFuncSetAttribute(gemm_mma<1>, cudaFuncAttributeMaxDynamicSharedMemorySize, gemm_smem);
    cudaFuncSetAttribute(attention_kernel, cudaFuncAttributeMaxDynamicSharedMemorySize, attn_smem);

    // 1) split inputs to bf16 hi/lo
    split_kernel<0><<<(M * E_ / 4 + 255) / 256, 256>>>(x, M * E_ / 4);
    split_kernel<1><<<(3 * E_ * E_ / 4 + 255) / 256, 256>>>(qkv_w, 3 * E_ * E_ / 4);
    split_kernel<2><<<(E_ * E_ / 4 + 255) / 256, 256>>>(out_w, E_ * E_ / 4);

    // 2) QKV projection -> q/k/v bf16 hi/lo [B,H,N,D]
    gemm_mma<0><<<dim3(3 * E_ / 128, M / 128), 256, gemm_smem>>>(qkv_b, nullptr, E_, 3 * E_);

    // 3) causal flash attention -> g_at hi/lo [B,N,E]
    attention_kernel<<<dim3(N_ / 64, B_ * H_), 128, attn_smem>>>();

    // 4) output projection -> out (fp32)
    gemm_mma<1><<<dim3(E_ / 128, M / 128), 256, gemm_smem>>>(out_b, out, E_, E_);
}